// round 8
// baseline (speedup 1.0000x reference)
#include <cuda_runtime.h>
#include <cuda_bf16.h>
#include <math.h>

#define EPS_CLAMP 1e-4f
#define BLK 128
#define WITEMS 64          // items per warp (2 per thread)
#define BITEMS (BLK * 2)   // items per block = 256
#define HALF 16            // items per flush phase

// ---------------------------------------------------------------------------
// Per-item math: vech v[6] -> Y = M * exp(A)  [9x3], all in registers.
// ---------------------------------------------------------------------------
__device__ __forceinline__ void compute_Y(const float v[6], const float M[27],
                                          float Y[9][3]) {
    const float a00 = v[0], a01 = v[1], a02 = v[2];
    const float a11 = v[3], a12 = v[4], a22 = v[5];

    // analytic eigenvalues (trig method), l0 >= l1 >= l2
    const float q   = (a00 + a11 + a22) * (1.0f / 3.0f);
    const float b00 = a00 - q, b11 = a11 - q, b22 = a22 - q;
    const float off2 = a01*a01 + a02*a02 + a12*a12;
    const float p2_half = 0.5f * (b00*b00 + b11*b11 + b22*b22) + off2;
    const float pp = sqrtf(p2_half * (1.0f / 3.0f));
    const float detB = b00 * (b11*b22 - a12*a12)
                     - a01 * (a01*b22 - a12*a02)
                     + a02 * (a01*a12 - b11*a02);
    const float pinv = __fdividef(1.0f, fmaxf(pp, 1e-30f));
    float r = 0.5f * detB * pinv * pinv * pinv;
    r = fminf(1.0f, fmaxf(-1.0f, r));
    const float phi = acosf(r) * (1.0f / 3.0f);
    const float l0 = q + 2.0f * pp * __cosf(phi);
    const float l2 = q + 2.0f * pp * __cosf(phi + 2.0943951023931953f);
    const float l1 = 3.0f * q - l0 - l2;

    // exp via Newton divided differences (expm1-stable)
    const float d01 = l0 - l1, d12 = l1 - l2, d02 = l0 - l2;
    const float e2  = __expf(l2);
    const float g12 = expm1f(d12);
    const float e1  = e2 * (g12 + 1.0f);
    const float f12 = (d12 > 1e-10f) ? e2 * __fdividef(g12, d12) : e2;
    const float g01 = expm1f(d01);
    const float e0  = e1 * (g01 + 1.0f);
    const float f01 = (d01 > 1e-10f) ? e1 * __fdividef(g01, d01) : e1;
    const float f012 = (d02 > 1e-10f) ? __fdividef(f01 - f12, d02) : 0.5f * e1;

    const float alpha = f012;
    const float beta  = f01 - f012 * (l0 + l1);
    const float gamma = e0 - f01 * l0 + f012 * (l0 * l1);

    // A^2 (symmetric)
    const float s00 = a00*a00 + a01*a01 + a02*a02;
    const float s01 = a00*a01 + a01*a11 + a02*a12;
    const float s02 = a00*a02 + a01*a12 + a02*a22;
    const float s11 = a01*a01 + a11*a11 + a12*a12;
    const float s12 = a01*a02 + a11*a12 + a12*a22;
    const float s22 = a02*a02 + a12*a12 + a22*a22;

    float x[3][3];
    x[0][0] = alpha*s00 + beta*a00 + gamma;
    x[0][1] = alpha*s01 + beta*a01;         x[1][0] = x[0][1];
    x[0][2] = alpha*s02 + beta*a02;         x[2][0] = x[0][2];
    x[1][1] = alpha*s11 + beta*a11 + gamma;
    x[1][2] = alpha*s12 + beta*a12;         x[2][1] = x[1][2];
    x[2][2] = alpha*s22 + beta*a22 + gamma;

    #pragma unroll
    for (int rr = 0; rr < 9; rr++) {
        const float m0 = M[rr*3+0], m1 = M[rr*3+1], m2 = M[rr*3+2];
        #pragma unroll
        for (int k = 0; k < 3; k++)
            Y[rr][k] = m0 * x[0][k] + m1 * x[1][k] + m2 * x[2][k];
    }
}

// ---------------------------------------------------------------------------
// Warp-autonomous SPDNet decoder, 2 items/thread for ILP, half-slice flush.
// ---------------------------------------------------------------------------
__global__ void __launch_bounds__(BLK)
spd_main_kernel(const float* __restrict__ vech,
                const float* __restrict__ W1,
                const float* __restrict__ W2,
                const float* __restrict__ W3,
                float* __restrict__ out, int B) {
    __shared__ __align__(16) float stage[4][HALF * 81];  // 4 x 5184B
    __shared__ float A1[25];
    __shared__ float W21[21];
    __shared__ float S7[49];
    __shared__ float sM[27];
    __shared__ float sC[81];

    const int t    = threadIdx.x;
    const int w    = t >> 5;
    const int lane = t & 31;
    const int item0 = blockIdx.x * BITEMS;
    const int nItems = min(BITEMS, B - item0);

    // ---- prep phase 0 ----
    if (t < 25) {
        int i = t / 5, j = t % 5;
        float s = 0.f;
        #pragma unroll
        for (int k = 0; k < 3; k++) s += W1[i*3+k] * W1[j*3+k];
        A1[t] = (i == j ? 1.0f : 0.0f) - s;
    } else if (t < 46) {
        int u = t - 25; int i = u / 3, k = u % 3;
        float s = 0.f;
        #pragma unroll
        for (int a = 0; a < 5; a++) s += W2[i*5+a] * W1[a*3+k];
        W21[u] = s;
    }
    __syncthreads();

    // ---- prep phase 1 ----
    if (t < 49) {
        int i = t / 7, j = t % 7;
        float s = 0.f;
        #pragma unroll
        for (int a = 0; a < 5; a++) {
            float ta = 0.f;
            #pragma unroll
            for (int b = 0; b < 5; b++) ta += A1[a*5+b] * W2[j*5+b];
            s += W2[i*5+a] * ta;
        }
        float w2ij = 0.f;
        #pragma unroll
        for (int a = 0; a < 5; a++) w2ij += W2[i*5+a] * W2[j*5+a];
        S7[t] = s + (i == j ? 1.0f : 0.0f) - w2ij;
    } else if (t < 76) {
        int u = t - 49; int r = u / 3, k = u % 3;
        float s = 0.f;
        #pragma unroll
        for (int a = 0; a < 7; a++) s += W3[r*7+a] * W21[a*3+k];
        sM[u] = s;
    }
    __syncthreads();

    // ---- prep phase 2 ----
    if (t < 81) {
        int i = t / 9, j = t % 9;
        float s = 0.f;
        #pragma unroll
        for (int a = 0; a < 7; a++) {
            float ta = 0.f;
            #pragma unroll
            for (int b = 0; b < 7; b++) ta += S7[a*7+b] * W3[j*7+b];
            s += W3[i*7+a] * ta;
        }
        float w3ij = 0.f;
        #pragma unroll
        for (int a = 0; a < 7; a++) w3ij += W3[i*7+a] * W3[j*7+a];
        sC[t] = EPS_CLAMP * (s + (i == j ? 1.0f : 0.0f) - w3ij);
    }
    __syncthreads();  // last block-wide barrier

    float M[27];
    #pragma unroll
    for (int i = 0; i < 27; i++) M[i] = sM[i];

    // ---- warp-local: warp owns WITEMS items ----
    const int wItem0 = item0 + w * WITEMS;
    const int wn = max(0, min(WITEMS, nItems - w * WITEMS));
    float* const slice = stage[w];  // HALF*81 = 1296 floats (>= 64*6 = 384)

    // Stage this warp's vech coalesced, redistribute
    if (wn == WITEMS) {
        #pragma unroll
        for (int k = 0; k < 12; k++)
            slice[k * 32 + lane] = vech[(size_t)wItem0 * 6 + k * 32 + lane];
    } else {
        for (int idx = lane; idx < wn * 6; idx += 32)
            slice[idx] = vech[(size_t)wItem0 * 6 + idx];
    }
    __syncwarp();
    float v0[6], v1[6];
    #pragma unroll
    for (int j = 0; j < 6; j++) v0[j] = slice[lane * 6 + j];
    #pragma unroll
    for (int j = 0; j < 6; j++) v1[j] = slice[(lane + 32) * 6 + j];
    __syncwarp();

    const bool active0 = lane < wn;
    const bool active1 = lane + 32 < wn;
    float Y0[9][3], Y1[9][3];
    if (active0) compute_Y(v0, M, Y0);
    if (active1) compute_Y(v1, M, Y1);
    __syncwarp();

    // ---- 4 flush phases of HALF items each ----
    #pragma unroll
    for (int p = 0; p < 4; p++) {
        const int base = p * HALF;
        const int hItems = max(0, min(HALF, wn - base));
        if (hItems <= 0) break;
        constexpr bool dummy = false; (void)dummy;

        const bool mine = ((lane >> 4) == (p & 1)) && (p < 2 ? active0 : active1);
        if (mine) {
            float (&Y)[9][3] = (p < 2) ? Y0 : Y1;
            float* st = &slice[(lane & 15) * 81];
            #pragma unroll
            for (int rr = 0; rr < 9; rr++) {
                #pragma unroll
                for (int cc = rr; cc < 9; cc++) {
                    const float val = Y[rr][0] * M[cc*3+0]
                                    + Y[rr][1] * M[cc*3+1]
                                    + Y[rr][2] * M[cc*3+2]
                                    + sC[rr*9+cc];
                    st[rr*9+cc] = val;
                    st[cc*9+rr] = val;
                }
            }
        }
        __syncwarp();

        if (hItems == HALF) {
            float4* o4 = reinterpret_cast<float4*>(out + ((size_t)wItem0 + base) * 81);
            const float4* s4 = reinterpret_cast<const float4*>(slice);
            // HALF*81/4 = 324 float4 over 32 lanes
            #pragma unroll
            for (int idx = lane; idx < (HALF * 81) / 4; idx += 32)
                o4[idx] = s4[idx];
        } else {
            float* ob = out + ((size_t)wItem0 + base) * 81;
            for (int idx = lane; idx < hItems * 81; idx += 32)
                ob[idx] = slice[idx];
        }
        __syncwarp();
    }
}

// ---------------------------------------------------------------------------
extern "C" void kernel_launch(void* const* d_in, const int* in_sizes, int n_in,
                              void* d_out, int out_size) {
    const float* vech = nullptr;
    const float* W1 = nullptr;
    const float* W2 = nullptr;
    const float* W3 = nullptr;
    int vech_elems = 0;
    for (int i = 0; i < n_in; i++) {
        int sz = in_sizes[i];
        if (sz == 15)      W1 = (const float*)d_in[i];
        else if (sz == 35) W2 = (const float*)d_in[i];
        else if (sz == 63) W3 = (const float*)d_in[i];
        else { vech = (const float*)d_in[i]; vech_elems = sz; }
    }
    int B = vech_elems / 6;
    int grid = (B + BITEMS - 1) / BITEMS;
    spd_main_kernel<<<grid, BLK>>>(vech, W1, W2, W3, (float*)d_out, B);
}

// round 9
// speedup vs baseline: 1.2054x; 1.2054x over previous
#include <cuda_runtime.h>
#include <cuda_bf16.h>
#include <math.h>

#define EPS_CLAMP 1e-4f
#define BLK 128

// ---------------------------------------------------------------------------
// Warp-autonomous SPDNet decoder (R5 structure) + instruction-diet math.
//   prep (block-wide, once): M = W3 W2 W1 [9x3], C9 [9x9] in smem.
//   Each warp owns 32 items; ONE flush phase with all 32 lanes storing
//   (issue-minimal transpose: 81 STS + 21 LDS.128 + 21 STG.128 per warp).
//   exp(A) via analytic eigenvalues + divided differences computed from
//   __expf with Taylor fallback (no expm1f / libm branches).
// ---------------------------------------------------------------------------
__global__ void __launch_bounds__(BLK)
spd_main_kernel(const float* __restrict__ vech,
                const float* __restrict__ W1,
                const float* __restrict__ W2,
                const float* __restrict__ W3,
                float* __restrict__ out, int B) {
    __shared__ __align__(16) float stage[BLK * 81];  // 4 warp slices of 32*81
    __shared__ float A1[25];
    __shared__ float W21[21];
    __shared__ float S7[49];
    __shared__ float sM[27];
    __shared__ float sC[81];

    const int t    = threadIdx.x;
    const int w    = t >> 5;
    const int lane = t & 31;
    const int item0 = blockIdx.x * BLK;
    const int nItems = min(BLK, B - item0);

    // ---- prep phase 0 ----
    if (t < 25) {
        int i = t / 5, j = t % 5;
        float s = 0.f;
        #pragma unroll
        for (int k = 0; k < 3; k++) s += W1[i*3+k] * W1[j*3+k];
        A1[t] = (i == j ? 1.0f : 0.0f) - s;
    } else if (t < 46) {
        int u = t - 25; int i = u / 3, k = u % 3;
        float s = 0.f;
        #pragma unroll
        for (int a = 0; a < 5; a++) s += W2[i*5+a] * W1[a*3+k];
        W21[u] = s;
    }
    __syncthreads();

    // ---- prep phase 1 ----
    if (t < 49) {
        int i = t / 7, j = t % 7;
        float s = 0.f;
        #pragma unroll
        for (int a = 0; a < 5; a++) {
            float ta = 0.f;
            #pragma unroll
            for (int b = 0; b < 5; b++) ta += A1[a*5+b] * W2[j*5+b];
            s += W2[i*5+a] * ta;
        }
        float w2ij = 0.f;
        #pragma unroll
        for (int a = 0; a < 5; a++) w2ij += W2[i*5+a] * W2[j*5+a];
        S7[t] = s + (i == j ? 1.0f : 0.0f) - w2ij;
    } else if (t < 76) {
        int u = t - 49; int r = u / 3, k = u % 3;
        float s = 0.f;
        #pragma unroll
        for (int a = 0; a < 7; a++) s += W3[r*7+a] * W21[a*3+k];
        sM[u] = s;
    }
    __syncthreads();

    // ---- prep phase 2 ----
    if (t < 81) {
        int i = t / 9, j = t % 9;
        float s = 0.f;
        #pragma unroll
        for (int a = 0; a < 7; a++) {
            float ta = 0.f;
            #pragma unroll
            for (int b = 0; b < 7; b++) ta += S7[a*7+b] * W3[j*7+b];
            s += W3[i*7+a] * ta;
        }
        float w3ij = 0.f;
        #pragma unroll
        for (int a = 0; a < 7; a++) w3ij += W3[i*7+a] * W3[j*7+a];
        sC[t] = EPS_CLAMP * (s + (i == j ? 1.0f : 0.0f) - w3ij);
    }
    __syncthreads();  // last block-wide barrier

    float M[27];
    #pragma unroll
    for (int i = 0; i < 27; i++) M[i] = sM[i];

    // ---- warp-local ----
    const int wItem0 = item0 + w * 32;
    const int wn = max(0, min(32, nItems - w * 32));
    float* const slice = &stage[w * 32 * 81];

    if (wn == 32) {
        #pragma unroll
        for (int k = 0; k < 6; k++)
            slice[k * 32 + lane] = vech[(size_t)wItem0 * 6 + k * 32 + lane];
    } else {
        for (int idx = lane; idx < wn * 6; idx += 32)
            slice[idx] = vech[(size_t)wItem0 * 6 + idx];
    }
    __syncwarp();
    float v[6];
    {   // float2 redistribute: 3 LDS.64 (8B-aligned since stride 6 is even)
        const float2* s2 = reinterpret_cast<const float2*>(slice);
        float2 p0 = s2[lane * 3 + 0];
        float2 p1 = s2[lane * 3 + 1];
        float2 p2 = s2[lane * 3 + 2];
        v[0] = p0.x; v[1] = p0.y; v[2] = p1.x;
        v[3] = p1.y; v[4] = p2.x; v[5] = p2.y;
    }
    __syncwarp();

    const bool active = lane < wn;
    if (active) {
        const float a00 = v[0], a01 = v[1], a02 = v[2];
        const float a11 = v[3], a12 = v[4], a22 = v[5];

        // ---- analytic eigenvalues (trig method), l0 >= l1 >= l2 ----
        const float q   = (a00 + a11 + a22) * (1.0f / 3.0f);
        const float b00 = a00 - q, b11 = a11 - q, b22 = a22 - q;
        const float off2 = a01*a01 + a02*a02 + a12*a12;
        const float p2_half = 0.5f * (b00*b00 + b11*b11 + b22*b22) + off2;
        const float pp = sqrtf(p2_half * (1.0f / 3.0f));
        const float detB = b00 * (b11*b22 - a12*a12)
                         - a01 * (a01*b22 - a12*a02)
                         + a02 * (a01*a12 - b11*a02);
        const float pinv = __fdividef(1.0f, fmaxf(pp, 1e-30f));
        float r = 0.5f * detB * pinv * pinv * pinv;
        r = fminf(1.0f, fmaxf(-1.0f, r));
        const float phi = acosf(r) * (1.0f / 3.0f);
        const float l0 = q + 2.0f * pp * __cosf(phi);
        const float l2 = q + 2.0f * pp * __cosf(phi + 2.0943951023931953f);
        const float l1 = 3.0f * q - l0 - l2;

        // ---- divided differences from __expf + Taylor fallback ----
        const float a = l0 - l1, b = l1 - l2, c = l0 - l2;   // all >= 0
        const float e0 = __expf(l0);
        const float e1 = __expf(l1);
        const float e2 = __expf(l2);
        // f01 = (e0-e1)/a ; small-a: e1*(1 + a/2 + a^2/6 + a^3/24)
        const float f01 = (a > 0.0625f)
            ? __fdividef(e0 - e1, a)
            : e1 * (1.0f + a * (0.5f + a * (0.16666667f + a * 0.041666667f)));
        // f12 = (e1-e2)/b ; small-b: e1*(1 - b/2 + b^2/6 - b^3/24)
        const float f12 = (b > 0.0625f)
            ? __fdividef(e1 - e2, b)
            : e1 * (1.0f - b * (0.5f - b * (0.16666667f - b * 0.041666667f)));
        // f012 = (f01-f12)/c ; small-c: e1*(1/2 + (a-b)/6 + (a^2-ab+b^2)/24)
        const float f012 = (c > 0.125f)
            ? __fdividef(f01 - f12, c)
            : e1 * (0.5f + (a - b) * 0.16666667f
                    + (a * a - a * b + b * b) * 0.041666667f);

        const float alpha = f012;
        const float beta  = f01 - f012 * (l0 + l1);
        const float gamma = e0 - f01 * l0 + f012 * (l0 * l1);

        // A^2 (symmetric)
        const float s00 = a00*a00 + a01*a01 + a02*a02;
        const float s01 = a00*a01 + a01*a11 + a02*a12;
        const float s02 = a00*a02 + a01*a12 + a02*a22;
        const float s11 = a01*a01 + a11*a11 + a12*a12;
        const float s12 = a01*a02 + a11*a12 + a12*a22;
        const float s22 = a02*a02 + a12*a12 + a22*a22;

        float x[3][3];
        x[0][0] = alpha*s00 + beta*a00 + gamma;
        x[0][1] = alpha*s01 + beta*a01;         x[1][0] = x[0][1];
        x[0][2] = alpha*s02 + beta*a02;         x[2][0] = x[0][2];
        x[1][1] = alpha*s11 + beta*a11 + gamma;
        x[1][2] = alpha*s12 + beta*a12;         x[2][1] = x[1][2];
        x[2][2] = alpha*s22 + beta*a22 + gamma;

        // Y = M * X3   [9,3]
        float Y[9][3];
        #pragma unroll
        for (int rr = 0; rr < 9; rr++) {
            const float m0 = M[rr*3+0], m1 = M[rr*3+1], m2 = M[rr*3+2];
            #pragma unroll
            for (int k = 0; k < 3; k++)
                Y[rr][k] = m0 * x[0][k] + m1 * x[1][k] + m2 * x[2][k];
        }

        // X9 = Y * M^T + C9 (symmetric) -> own slice (ONE phase, all lanes)
        float* st = &slice[lane * 81];
        #pragma unroll
        for (int rr = 0; rr < 9; rr++) {
            #pragma unroll
            for (int cc = rr; cc < 9; cc++) {
                const float val = Y[rr][0] * M[cc*3+0]
                                + Y[rr][1] * M[cc*3+1]
                                + Y[rr][2] * M[cc*3+2]
                                + sC[rr*9+cc];
                st[rr*9+cc] = val;
                st[cc*9+rr] = val;
            }
        }
    }
    __syncwarp();

    // Coalesced copy of this warp's slice (2592 floats = 648 float4)
    if (wn == 32) {
        float4* o4 = reinterpret_cast<float4*>(out + (size_t)wItem0 * 81);
        const float4* s4 = reinterpret_cast<const float4*>(slice);
        #pragma unroll 7
        for (int idx = lane; idx < (32 * 81) / 4; idx += 32)
            o4[idx] = s4[idx];
    } else if (wn > 0) {
        float* ob = out + (size_t)wItem0 * 81;
        for (int idx = lane; idx < wn * 81; idx += 32)
            ob[idx] = slice[idx];
    }
}

// ---------------------------------------------------------------------------
extern "C" void kernel_launch(void* const* d_in, const int* in_sizes, int n_in,
                              void* d_out, int out_size) {
    const float* vech = nullptr;
    const float* W1 = nullptr;
    const float* W2 = nullptr;
    const float* W3 = nullptr;
    int vech_elems = 0;
    for (int i = 0; i < n_in; i++) {
        int sz = in_sizes[i];
        if (sz == 15)      W1 = (const float*)d_in[i];
        else if (sz == 35) W2 = (const float*)d_in[i];
        else if (sz == 63) W3 = (const float*)d_in[i];
        else { vech = (const float*)d_in[i]; vech_elems = sz; }
    }
    int B = vech_elems / 6;
    int grid = (B + BLK - 1) / BLK;
    spd_main_kernel<<<grid, BLK>>>(vech, W1, W2, W3, (float*)d_out, B);
}

// round 11
// speedup vs baseline: 1.2227x; 1.0143x over previous
#include <cuda_runtime.h>
#include <cuda_bf16.h>
#include <math.h>

#define EPS_CLAMP 1e-4f
#define BLK 64            // 2 warps -> ~21.3KB smem -> 10 blocks/SM (62% occ)

// ---------------------------------------------------------------------------
// Warp-autonomous SPDNet decoder.
//   Key identity: the accumulated ReEig constant telescopes:
//     W3W2(I-W1W1t)W2tW3t + W3(I-W2W2t)W3t + (I-W3W3t) = I - M Mt,  M=W3W2W1
//   so prep is just M = W3(W2 W1) and C9 = EPS*(I - M Mt).
//   Each warp owns 32 items: analytic 3x3 eigenvalues + divided differences
//   (exp(A) = aA^2+bA+cI), congruence to 9x9, one-phase smem transpose,
//   coalesced float4 stores. Only __syncwarp after prep.
// ---------------------------------------------------------------------------
__global__ void __launch_bounds__(BLK)
spd_main_kernel(const float* __restrict__ vech,
                const float* __restrict__ W1,
                const float* __restrict__ W2,
                const float* __restrict__ W3,
                float* __restrict__ out, int B) {
    __shared__ __align__(16) float stage[(BLK / 32) * 32 * 81];  // 20736 B
    __shared__ float W21[21];            // W2 @ W1 [7,3]
    __shared__ float sM[27];             // M = W3 W2 W1 [9,3]
    __shared__ float sC[(BLK / 32)][81]; // per-warp copy of EPS*(I - M Mt)

    const int t    = threadIdx.x;
    const int w    = t >> 5;
    const int lane = t & 31;
    const int item0 = blockIdx.x * BLK;
    const int nItems = min(BLK, B - item0);

    // ---- prep A: W21 = W2 @ W1 ----
    if (t < 21) {
        int i = t / 3, k = t % 3;
        float s = 0.f;
        #pragma unroll
        for (int a = 0; a < 5; a++) s += W2[i*5+a] * W1[a*3+k];
        W21[t] = s;
    }
    __syncthreads();

    // ---- prep B: M = W3 @ W21 ----
    if (t < 27) {
        int r = t / 3, k = t % 3;
        float s = 0.f;
        #pragma unroll
        for (int a = 0; a < 7; a++) s += W3[r*7+a] * W21[a*3+k];
        sM[t] = s;
    }
    __syncthreads();   // last block-wide barrier

    // M into registers (27 broadcast LDS)
    float M[27];
    #pragma unroll
    for (int i = 0; i < 27; i++) M[i] = sM[i];

    // ---- per-warp C9 = EPS*(I - M Mt): warps stay autonomous ----
    {
        float* cw = sC[w];
        for (int u = lane; u < 81; u += 32) {
            int i = u / 9, j = u % 9;
            float d = M[i*3+0]*M[j*3+0] + M[i*3+1]*M[j*3+1] + M[i*3+2]*M[j*3+2];
            cw[u] = EPS_CLAMP * ((i == j ? 1.0f : 0.0f) - d);
        }
    }

    // ---- warp-local ----
    const int wItem0 = item0 + w * 32;
    const int wn = max(0, min(32, nItems - w * 32));
    float* const slice = &stage[w * 32 * 81];
    const float* const cw = sC[w];

    if (wn == 32) {
        #pragma unroll
        for (int k = 0; k < 6; k++)
            slice[k * 32 + lane] = vech[(size_t)wItem0 * 6 + k * 32 + lane];
    } else {
        for (int idx = lane; idx < wn * 6; idx += 32)
            slice[idx] = vech[(size_t)wItem0 * 6 + idx];
    }
    __syncwarp();
    float v[6];
    {   // float2 redistribute: 3 LDS.64
        const float2* s2 = reinterpret_cast<const float2*>(slice);
        float2 p0 = s2[lane * 3 + 0];
        float2 p1 = s2[lane * 3 + 1];
        float2 p2 = s2[lane * 3 + 2];
        v[0] = p0.x; v[1] = p0.y; v[2] = p1.x;
        v[3] = p1.y; v[4] = p2.x; v[5] = p2.y;
    }
    __syncwarp();

    const bool active = lane < wn;
    if (active) {
        const float a00 = v[0], a01 = v[1], a02 = v[2];
        const float a11 = v[3], a12 = v[4], a22 = v[5];

        // ---- analytic eigenvalues (trig method), l0 >= l1 >= l2 ----
        const float q   = (a00 + a11 + a22) * (1.0f / 3.0f);
        const float b00 = a00 - q, b11 = a11 - q, b22 = a22 - q;
        const float off2 = a01*a01 + a02*a02 + a12*a12;
        const float p2_half = 0.5f * (b00*b00 + b11*b11 + b22*b22) + off2;
        const float pp = sqrtf(p2_half * (1.0f / 3.0f));
        const float detB = b00 * (b11*b22 - a12*a12)
                         - a01 * (a01*b22 - a12*a02)
                         + a02 * (a01*a12 - b11*a02);
        const float pinv = __fdividef(1.0f, fmaxf(pp, 1e-30f));
        float r = 0.5f * detB * pinv * pinv * pinv;
        r = fminf(1.0f, fmaxf(-1.0f, r));
        const float phi = acosf(r) * (1.0f / 3.0f);
        const float l0 = q + 2.0f * pp * __cosf(phi);
        const float l2 = q + 2.0f * pp * __cosf(phi + 2.0943951023931953f);
        const float l1 = 3.0f * q - l0 - l2;

        // ---- divided differences from __expf + Taylor fallback ----
        const float a = l0 - l1, b = l1 - l2, c = l0 - l2;   // all >= 0
        const float e0 = __expf(l0);
        const float e1 = __expf(l1);
        const float e2 = __expf(l2);
        const float f01 = (a > 0.0625f)
            ? __fdividef(e0 - e1, a)
            : e1 * (1.0f + a * (0.5f + a * (0.16666667f + a * 0.041666667f)));
        const float f12 = (b > 0.0625f)
            ? __fdividef(e1 - e2, b)
            : e1 * (1.0f - b * (0.5f - b * (0.16666667f - b * 0.041666667f)));
        const float f012 = (c > 0.125f)
            ? __fdividef(f01 - f12, c)
            : e1 * (0.5f + (a - b) * 0.16666667f
                    + (a * a - a * b + b * b) * 0.041666667f);

        const float alpha = f012;
        const float beta  = f01 - f012 * (l0 + l1);
        const float gamma = e0 - f01 * l0 + f012 * (l0 * l1);

        // A^2 (symmetric)
        const float s00 = a00*a00 + a01*a01 + a02*a02;
        const float s01 = a00*a01 + a01*a11 + a02*a12;
        const float s02 = a00*a02 + a01*a12 + a02*a22;
        const float s11 = a01*a01 + a11*a11 + a12*a12;
        const float s12 = a01*a02 + a11*a12 + a12*a22;
        const float s22 = a02*a02 + a12*a12 + a22*a22;

        float x[3][3];
        x[0][0] = alpha*s00 + beta*a00 + gamma;
        x[0][1] = alpha*s01 + beta*a01;         x[1][0] = x[0][1];
        x[0][2] = alpha*s02 + beta*a02;         x[2][0] = x[0][2];
        x[1][1] = alpha*s11 + beta*a11 + gamma;
        x[1][2] = alpha*s12 + beta*a12;         x[2][1] = x[1][2];
        x[2][2] = alpha*s22 + beta*a22 + gamma;

        // Y = M * X3   [9,3]
        float Y[9][3];
        #pragma unroll
        for (int rr = 0; rr < 9; rr++) {
            const float m0 = M[rr*3+0], m1 = M[rr*3+1], m2 = M[rr*3+2];
            #pragma unroll
            for (int k = 0; k < 3; k++)
                Y[rr][k] = m0 * x[0][k] + m1 * x[1][k] + m2 * x[2][k];
        }

        // X9 = Y * M^T + C9 (symmetric) -> own slice (ONE phase, all lanes)
        float* st = &slice[lane * 81];
        #pragma unroll
        for (int rr = 0; rr < 9; rr++) {
            #pragma unroll
            for (int cc = rr; cc < 9; cc++) {
                const float val = Y[rr][0] * M[cc*3+0]
                                + Y[rr][1] * M[cc*3+1]
                                + Y[rr][2] * M[cc*3+2]
                                + cw[rr*9+cc];
                st[rr*9+cc] = val;
                st[cc*9+rr] = val;
            }
        }
    }
    __syncwarp();

    // Coalesced copy of this warp's slice (2592 floats = 648 float4)
    if (wn == 32) {
        float4* o4 = reinterpret_cast<float4*>(out + (size_t)wItem0 * 81);
        const float4* s4 = reinterpret_cast<const float4*>(slice);
        #pragma unroll 7
        for (int idx = lane; idx < (32 * 81) / 4; idx += 32)
            o4[idx] = s4[idx];
    } else if (wn > 0) {
        float* ob = out + (size_t)wItem0 * 81;
        for (int idx = lane; idx < wn * 81; idx += 32)
            ob[idx] = slice[idx];
    }
}

// ---------------------------------------------------------------------------
extern "C" void kernel_launch(void* const* d_in, const int* in_sizes, int n_in,
                              void* d_out, int out_size) {
    const float* vech = nullptr;
    const float* W1 = nullptr;
    const float* W2 = nullptr;
    const float* W3 = nullptr;
    int vech_elems = 0;
    for (int i = 0; i < n_in; i++) {
        int sz = in_sizes[i];
        if (sz == 15)      W1 = (const float*)d_in[i];
        else if (sz == 35) W2 = (const float*)d_in[i];
        else if (sz == 63) W3 = (const float*)d_in[i];
        else { vech = (const float*)d_in[i]; vech_elems = sz; }
    }
    int B = vech_elems / 6;
    int grid = (B + BLK - 1) / BLK;
    spd_main_kernel<<<grid, BLK>>>(vech, W1, W2, W3, (float*)d_out, B);
}